// round 2
// baseline (speedup 1.0000x reference)
#include <cuda_runtime.h>
#include <math.h>

#define BB   128   // batch
#define TSEQ 512   // sequence length
#define DD   256   // model dim
#define HH   256   // lstm hidden
#define NG   1024  // 4*HH
#define NBLK 384   // persistent LSTM grid size (6 layer-steps x 64 blocks)

// ---------------- device scratch (no allocs allowed) ----------------
__device__ float g_x[BB * TSEQ * DD];          // activations
__device__ float g_feats[BB * TSEQ * DD];      // conv output
__device__ float g_Wt[2 * 3 * 512 * NG];       // transposed [dir*3+l][k(512)][j(256)*4+gate]
__device__ float g_cur[2 * 2 * 2 * BB * DD];   // [dir][stage(0,1)][parity][b][d]
__device__ float g_h[2 * 3 * 2 * BB * HH];     // [dir*3+l][pingpong][b][h]
__device__ float g_c[2 * 3 * BB * HH];         // [dir*3+l][b][h]
__device__ unsigned g_sync;                    // grid barrier counter

// ---------------- embedding gather ----------------
__global__ void k_embed(const int* __restrict__ tokens, const float* __restrict__ E) {
    int row = blockIdx.x;                 // b*TSEQ + t
    int tok = tokens[row];
    const float4* src = reinterpret_cast<const float4*>(E) + (size_t)tok * (DD / 4);
    float4* dst = reinterpret_cast<float4*>(g_x) + (size_t)row * (DD / 4);
    dst[threadIdx.x] = src[threadIdx.x];
}

// ---------------- conv bank: feats = tanh(c3)+tanh(c5)+tanh(c7)+x ----------------
__global__ void __launch_bounds__(256) k_conv(
    const float* __restrict__ W3, const float* __restrict__ W5,
    const float* __restrict__ W7, const float* __restrict__ bconv, int iter)
{
    const int o  = threadIdx.x;
    const int t0 = blockIdx.x * 16;
    const int b  = blockIdx.y;

    __shared__ float sx[22][DD];  // t0-3 .. t0+18
    const float* xb = g_x + (size_t)b * TSEQ * DD;
    for (int e = threadIdx.x; e < 22 * DD; e += 256) {
        int r = e >> 8, c = e & 255;
        int tg = t0 - 3 + r;
        sx[r][c] = (tg >= 0 && tg < TSEQ) ? xb[(size_t)tg * DD + c] : 0.f;
    }
    __syncthreads();

    float acc3[16], acc5[16], acc7[16];
#pragma unroll
    for (int t = 0; t < 16; ++t) { acc3[t] = 0.f; acc5[t] = 0.f; acc7[t] = 0.f; }

    const float* W3i = W3 + (size_t)iter * 3 * DD * DD;
    const float* W5i = W5 + (size_t)iter * 5 * DD * DD;
    const float* W7i = W7 + (size_t)iter * 7 * DD * DD;

    for (int c = 0; c < DD; ++c) {
        float xr[22];
#pragma unroll
        for (int s = 0; s < 22; ++s) xr[s] = sx[s][c];
#pragma unroll
        for (int k = 0; k < 7; ++k) {
            float w = W7i[((size_t)k * DD + c) * DD + o];
#pragma unroll
            for (int t = 0; t < 16; ++t) acc7[t] = fmaf(xr[t + k], w, acc7[t]);
        }
#pragma unroll
        for (int k = 0; k < 5; ++k) {
            float w = W5i[((size_t)k * DD + c) * DD + o];
#pragma unroll
            for (int t = 0; t < 16; ++t) acc5[t] = fmaf(xr[t + k + 1], w, acc5[t]);
        }
#pragma unroll
        for (int k = 0; k < 3; ++k) {
            float w = W3i[((size_t)k * DD + c) * DD + o];
#pragma unroll
            for (int t = 0; t < 16; ++t) acc3[t] = fmaf(xr[t + k + 2], w, acc3[t]);
        }
    }

    float b3 = bconv[(iter * 3 + 0) * DD + o];
    float b5 = bconv[(iter * 3 + 1) * DD + o];
    float b7 = bconv[(iter * 3 + 2) * DD + o];
    float* fb = g_feats + ((size_t)b * TSEQ + t0) * DD + o;
#pragma unroll
    for (int t = 0; t < 16; ++t) {
        fb[(size_t)t * DD] = tanhf(acc3[t] + b3) + tanhf(acc5[t] + b5) +
                             tanhf(acc7[t] + b7) + sx[t + 3][o];
    }
}

// ---------------- layernorm: x = LN(feats)*gamma + beta ----------------
__global__ void k_ln(const float* __restrict__ gamma, const float* __restrict__ beta, int iter) {
    int wid = threadIdx.x >> 5, lane = threadIdx.x & 31;
    int row = blockIdx.x * 8 + wid;
    const float4* f = reinterpret_cast<const float4*>(g_feats + (size_t)row * DD);
    float4 v0 = f[lane];
    float4 v1 = f[32 + lane];
    float s = v0.x + v0.y + v0.z + v0.w + v1.x + v1.y + v1.z + v1.w;
    float q = v0.x*v0.x + v0.y*v0.y + v0.z*v0.z + v0.w*v0.w +
              v1.x*v1.x + v1.y*v1.y + v1.z*v1.z + v1.w*v1.w;
#pragma unroll
    for (int ofs = 16; ofs; ofs >>= 1) {
        s += __shfl_xor_sync(0xffffffffu, s, ofs);
        q += __shfl_xor_sync(0xffffffffu, q, ofs);
    }
    float mean = s * (1.f / 256.f);
    float var  = q * (1.f / 256.f) - mean * mean;
    float rstd = rsqrtf(var + 1e-3f);

    const float* ga = gamma + iter * DD;
    const float* be = beta + iter * DD;
    float4* xo = reinterpret_cast<float4*>(g_x + (size_t)row * DD);
    int c0 = lane * 4;
    float4 r0, r1;
    r0.x = (v0.x - mean) * rstd * ga[c0 + 0] + be[c0 + 0];
    r0.y = (v0.y - mean) * rstd * ga[c0 + 1] + be[c0 + 1];
    r0.z = (v0.z - mean) * rstd * ga[c0 + 2] + be[c0 + 2];
    r0.w = (v0.w - mean) * rstd * ga[c0 + 3] + be[c0 + 3];
    r1.x = (v1.x - mean) * rstd * ga[128 + c0 + 0] + be[128 + c0 + 0];
    r1.y = (v1.y - mean) * rstd * ga[128 + c0 + 1] + be[128 + c0 + 1];
    r1.z = (v1.z - mean) * rstd * ga[128 + c0 + 2] + be[128 + c0 + 2];
    r1.w = (v1.w - mean) * rstd * ga[128 + c0 + 3] + be[128 + c0 + 3];
    xo[lane] = r0;
    xo[32 + lane] = r1;
}

// ---------------- weight pre-transpose ----------------
__global__ void k_transpose(const float* __restrict__ Wx, const float* __restrict__ Wh) {
    int idx = blockIdx.x * 256 + threadIdx.x;
    if (idx >= 2 * 3 * 512 * NG) return;
    int dl  = idx / (512 * NG);
    int rem = idx % (512 * NG);
    int k   = rem / NG;
    int cp  = rem % NG;       // cp = j*4 + g
    int j = cp >> 2, g = cp & 3;
    int n = g * 256 + j;
    float v = (k < 256) ? Wx[(size_t)dl * 256 * NG + (size_t)k * NG + n]
                        : Wh[(size_t)dl * 256 * NG + (size_t)(k - 256) * NG + n];
    g_Wt[idx] = v;
}

__global__ void k_zero() {
    int i = blockIdx.x * 256 + threadIdx.x;
    if (i < 2 * 3 * 2 * BB * HH) g_h[i] = 0.f;
    if (i < 2 * 3 * BB * HH)     g_c[i] = 0.f;
    if (i == 0) g_sync = 0u;
}

// ---------------- persistent wavefront LSTM ----------------
// 384 blocks: ls = blockIdx.x/64 in [0,6): dir = ls&1, layer = ls>>1.
// Wavefront w: layer processes t = w - layer. One grid barrier per wavefront.
__global__ void __launch_bounds__(256, 3) k_lstm_persist(
    const float* __restrict__ blstm, float* __restrict__ out)
{
    const int bx    = blockIdx.x;
    const int ls    = bx >> 6;
    const int dir   = ls & 1;
    const int layer = ls >> 1;
    const int sub   = bx & 63;
    const int j0    = (sub & 15) * 16;
    const int m0    = (sub >> 4) * 32;
    const int tid   = threadIdx.x;
    const int j     = tid & 15;
    const int mg    = tid >> 4;
    const int dl    = dir * 3 + layer;

    __shared__ float sA[32][33];
    __shared__ float sW[32][64];

    const float* Wl = g_Wt + (size_t)dl * 512 * NG + j0 * 4;
    const int col = j0 + j;
    const float* bbias = blstm + (size_t)dl * NG;
    const float bi  = bbias[col];
    const float bf_ = bbias[256 + col];
    const float bg  = bbias[512 + col];
    const float bo  = bbias[768 + col];
    float* cbuf = g_c + (size_t)dl * BB * HH;

    const unsigned nb = gridDim.x;

    for (int w = 0; w < TSEQ + 2; ++w) {
        const int t = w - layer;
        if (t >= 0 && t < TSEQ) {
            const int tt = dir ? (TSEQ - 1 - t) : t;
            const int rp = t & 1, wp = rp ^ 1;
            const float* hin = g_h + (size_t)(dl * 2 + rp) * BB * HH;
            // cur input: layer l>0 reads stage l-1 at parity t&1
            const float* cursrc = g_cur +
                (size_t)((dir * 2 + (layer - 1)) * 2 + (t & 1)) * BB * DD;
            // cur output: layer l<2 writes stage l at parity t&1
            float* curdst = g_cur +
                (size_t)((dir * 2 + layer) * 2 + (t & 1)) * BB * DD;

            float4 acc0 = {0.f, 0.f, 0.f, 0.f};
            float4 acc1 = {0.f, 0.f, 0.f, 0.f};

            for (int kc = 0; kc < 512; kc += 32) {
#pragma unroll
                for (int r = 0; r < 4; ++r) {
                    int e = tid + r * 256;
                    int ml = e >> 5, k = e & 31;
                    int kk = kc + k;
                    int m = m0 + ml;
                    float v;
                    if (kk < 256) {
                        v = (layer == 0)
                            ? g_x[((size_t)m * TSEQ + tt) * DD + kk]
                            : __ldcg(cursrc + (size_t)m * DD + kk);
                    } else {
                        v = __ldcg(hin + (size_t)m * HH + (kk - 256));
                    }
                    sA[k][ml] = v;
                }
#pragma unroll
                for (int r = 0; r < 8; ++r) {
                    int e = tid + r * 256;
                    int k = e >> 6, c2 = e & 63;
                    sW[k][c2] = Wl[(size_t)(kc + k) * NG + c2];
                }
                __syncthreads();
#pragma unroll
                for (int k = 0; k < 32; ++k) {
                    float a0 = sA[k][mg * 2];
                    float a1 = sA[k][mg * 2 + 1];
                    float4 wv = *reinterpret_cast<const float4*>(&sW[k][j * 4]);
                    acc0.x = fmaf(a0, wv.x, acc0.x); acc0.y = fmaf(a0, wv.y, acc0.y);
                    acc0.z = fmaf(a0, wv.z, acc0.z); acc0.w = fmaf(a0, wv.w, acc0.w);
                    acc1.x = fmaf(a1, wv.x, acc1.x); acc1.y = fmaf(a1, wv.y, acc1.y);
                    acc1.z = fmaf(a1, wv.z, acc1.z); acc1.w = fmaf(a1, wv.w, acc1.w);
                }
                __syncthreads();
            }

            float* hout = g_h + (size_t)(dl * 2 + wp) * BB * HH;
#pragma unroll
            for (int im = 0; im < 2; ++im) {
                int m = m0 + mg * 2 + im;
                float4 a = im ? acc1 : acc0;
                float zi = a.x + bi, zf = a.y + bf_, zg = a.z + bg, zo = a.w + bo;
                float ig = 1.f / (1.f + expf(-zi));
                float fg = 1.f / (1.f + expf(-zf));
                float gg = tanhf(zg);
                float og = 1.f / (1.f + expf(-zo));
                float cp = cbuf[(size_t)m * HH + col];
                float cn = fg * cp + ig * gg;
                float hn = og * tanhf(cn);
                cbuf[(size_t)m * HH + col] = cn;
                hout[(size_t)m * HH + col] = hn;
                float ain = (layer == 0)
                    ? g_x[((size_t)m * TSEQ + tt) * DD + col]
                    : __ldcg(cursrc + (size_t)m * DD + col);
                float cu = ain + hn;
                if (layer == 2)
                    out[((size_t)m * TSEQ + tt) * 512 + dir * 256 + col] = cu;
                else
                    curdst[(size_t)m * DD + col] = cu;
            }
        }

        // ---- grid barrier (sense-free monotonic counter) ----
        __syncthreads();
        __threadfence();
        if (tid == 0) {
            atomicAdd(&g_sync, 1u);
            unsigned target = nb * (unsigned)(w + 1);
            while (*(volatile unsigned*)&g_sync < target) __nanosleep(64);
        }
        __syncthreads();
    }
}

// ---------------- final states ----------------
__global__ void k_states(float* __restrict__ out) {
    int idx = blockIdx.x * 256 + threadIdx.x;
    if (idx >= 2 * 3 * BB * HH) return;
    int j  = idx & 255;
    int m  = (idx >> 8) & 127;
    int dl = idx >> 15;
    const size_t SEQ = (size_t)BB * TSEQ * 512;
    const size_t SH  = 2 * 3 * BB * HH;
    out[SEQ + idx]      = g_h[(size_t)(dl * 2 + 0) * BB * HH + (size_t)m * HH + j];
    out[SEQ + SH + idx] = g_c[(size_t)dl * BB * HH + (size_t)m * HH + j];
}

// ---------------- launch (9 graph nodes) ----------------
extern "C" void kernel_launch(void* const* d_in, const int* in_sizes, int n_in,
                              void* d_out, int out_size) {
    const int*   tokens = (const int*)d_in[0];
    const float* E      = (const float*)d_in[1];
    const float* W3     = (const float*)d_in[2];
    const float* W5     = (const float*)d_in[3];
    const float* W7     = (const float*)d_in[4];
    const float* bconv  = (const float*)d_in[5];
    const float* gamma  = (const float*)d_in[6];
    const float* beta   = (const float*)d_in[7];
    const float* Wx     = (const float*)d_in[8];
    const float* Wh     = (const float*)d_in[9];
    const float* blstm  = (const float*)d_in[10];
    float* out = (float*)d_out;

    k_embed<<<BB * TSEQ, 64>>>(tokens, E);
    for (int it = 0; it < 2; ++it) {
        k_conv<<<dim3(TSEQ / 16, BB), 256>>>(W3, W5, W7, bconv, it);
        k_ln<<<BB * TSEQ / 8, 256>>>(gamma, beta, it);
    }
    k_transpose<<<(2 * 3 * 512 * NG + 255) / 256, 256>>>(Wx, Wh);
    k_zero<<<1536, 256>>>();
    k_lstm_persist<<<NBLK, 256>>>(blstm, out);
    k_states<<<768, 256>>>(out);
}

// round 3
// speedup vs baseline: 1.6428x; 1.6428x over previous
#include <cuda_runtime.h>
#include <math.h>

#define BB   128   // batch
#define TSEQ 512   // sequence length
#define DD   256   // model dim
#define HH   256   // lstm hidden
#define NG   1024  // 4*HH
#define NBLK 384   // persistent LSTM grid (6 layer-steps x 64 tiles)

typedef unsigned long long u64;

// ---- packed f32x2 helpers (Blackwell dual-rate fp32 path) ----
__device__ __forceinline__ u64 pk2(float lo, float hi) {
    u64 r; asm("mov.b64 %0, {%1,%2};" : "=l"(r) : "f"(lo), "f"(hi)); return r;
}
__device__ __forceinline__ u64 ff2(u64 a, u64 b, u64 c) {  // a*b + c (per half)
    u64 d; asm("fma.rn.f32x2 %0, %1, %2, %3;" : "=l"(d) : "l"(a), "l"(b), "l"(c));
    return d;
}
__device__ __forceinline__ float2 up2(u64 v) {
    float2 f; asm("mov.b64 {%0,%1}, %2;" : "=f"(f.x), "=f"(f.y) : "l"(v)); return f;
}

// ---------------- device scratch ----------------
__device__ float g_x[BB * TSEQ * DD];
__device__ float g_feats[BB * TSEQ * DD];
__device__ float g_Wt[2 * 3 * 512 * NG];       // [dl][k(512)][j(256)*4+gate]
__device__ float g_cur[2 * 2 * 2 * BB * DD];   // [dir][stage][parity][b][d]
__device__ float g_h[2 * 3 * 2 * BB * HH];     // [dl][pingpong][b][h]
__device__ float g_c[2 * 3 * BB * HH];
__device__ unsigned g_sync;

// ---------------- embedding gather ----------------
__global__ void k_embed(const int* __restrict__ tokens, const float* __restrict__ E) {
    int row = blockIdx.x;
    int tok = tokens[row];
    const float4* src = reinterpret_cast<const float4*>(E) + (size_t)tok * (DD / 4);
    float4* dst = reinterpret_cast<float4*>(g_x) + (size_t)row * (DD / 4);
    dst[threadIdx.x] = src[threadIdx.x];
}

// ---------------- conv bank (FFMA2): feats = tanh(c3)+tanh(c5)+tanh(c7)+x ----
// 256 threads: thread = output channel o. 16-t tile paired as (t, t+8).
__global__ void __launch_bounds__(256, 2) k_conv(
    const float* __restrict__ W3, const float* __restrict__ W5,
    const float* __restrict__ W7, const float* __restrict__ bconv, int iter)
{
    const int o  = threadIdx.x;
    const int t0 = blockIdx.x * 16;
    const int b  = blockIdx.y;

    __shared__ float sx[DD][25];  // [c][t-window 22], pad 25 (odd, conflict-free)
    const float* xb = g_x + (size_t)b * TSEQ * DD;
#pragma unroll
    for (int r = 0; r < 22; ++r) {
        int tg = t0 - 3 + r;
        sx[o][r] = (tg >= 0 && tg < TSEQ) ? xb[(size_t)tg * DD + o] : 0.f;
    }
    __syncthreads();

    u64 acc3[8], acc5[8], acc7[8];
    const u64 z = pk2(0.f, 0.f);
#pragma unroll
    for (int i = 0; i < 8; ++i) { acc3[i] = z; acc5[i] = z; acc7[i] = z; }

    const float* W3i = W3 + (size_t)iter * 3 * DD * DD + o;
    const float* W5i = W5 + (size_t)iter * 5 * DD * DD + o;
    const float* W7i = W7 + (size_t)iter * 7 * DD * DD + o;

    for (int c = 0; c < DD; ++c) {
        // stride-8 x pairs {x[c][j], x[c][j+8]}, shared by all taps
        u64 xp[14];
#pragma unroll
        for (int i = 0; i < 14; ++i) xp[i] = pk2(sx[c][i], sx[c][i + 8]);

#pragma unroll
        for (int k = 0; k < 7; ++k) {
            float w = W7i[((size_t)k * DD + c) * DD];
            u64 ww = pk2(w, w);
#pragma unroll
            for (int i = 0; i < 8; ++i) acc7[i] = ff2(xp[i + k], ww, acc7[i]);
        }
#pragma unroll
        for (int k = 0; k < 5; ++k) {
            float w = W5i[((size_t)k * DD + c) * DD];
            u64 ww = pk2(w, w);
#pragma unroll
            for (int i = 0; i < 8; ++i) acc5[i] = ff2(xp[i + k + 1], ww, acc5[i]);
        }
#pragma unroll
        for (int k = 0; k < 3; ++k) {
            float w = W3i[((size_t)k * DD + c) * DD];
            u64 ww = pk2(w, w);
#pragma unroll
            for (int i = 0; i < 8; ++i) acc3[i] = ff2(xp[i + k + 2], ww, acc3[i]);
        }
    }

    float b3 = bconv[(iter * 3 + 0) * DD + o];
    float b5 = bconv[(iter * 3 + 1) * DD + o];
    float b7 = bconv[(iter * 3 + 2) * DD + o];
    float* fb = g_feats + ((size_t)b * TSEQ + t0) * DD + o;
#pragma unroll
    for (int i = 0; i < 8; ++i) {
        float2 a3 = up2(acc3[i]), a5 = up2(acc5[i]), a7 = up2(acc7[i]);
        fb[(size_t)i * DD] = tanhf(a3.x + b3) + tanhf(a5.x + b5) +
                             tanhf(a7.x + b7) + sx[o][i + 3];
        fb[(size_t)(i + 8) * DD] = tanhf(a3.y + b3) + tanhf(a5.y + b5) +
                                   tanhf(a7.y + b7) + sx[o][i + 11];
    }
}

// ---------------- layernorm ----------------
__global__ void k_ln(const float* __restrict__ gamma, const float* __restrict__ beta, int iter) {
    int wid = threadIdx.x >> 5, lane = threadIdx.x & 31;
    int row = blockIdx.x * 8 + wid;
    const float4* f = reinterpret_cast<const float4*>(g_feats + (size_t)row * DD);
    float4 v0 = f[lane];
    float4 v1 = f[32 + lane];
    float s = v0.x + v0.y + v0.z + v0.w + v1.x + v1.y + v1.z + v1.w;
    float q = v0.x*v0.x + v0.y*v0.y + v0.z*v0.z + v0.w*v0.w +
              v1.x*v1.x + v1.y*v1.y + v1.z*v1.z + v1.w*v1.w;
#pragma unroll
    for (int ofs = 16; ofs; ofs >>= 1) {
        s += __shfl_xor_sync(0xffffffffu, s, ofs);
        q += __shfl_xor_sync(0xffffffffu, q, ofs);
    }
    float mean = s * (1.f / 256.f);
    float var  = q * (1.f / 256.f) - mean * mean;
    float rstd = rsqrtf(var + 1e-3f);

    const float* ga = gamma + iter * DD;
    const float* be = beta + iter * DD;
    float4* xo = reinterpret_cast<float4*>(g_x + (size_t)row * DD);
    int c0 = lane * 4;
    float4 r0, r1;
    r0.x = (v0.x - mean) * rstd * ga[c0 + 0] + be[c0 + 0];
    r0.y = (v0.y - mean) * rstd * ga[c0 + 1] + be[c0 + 1];
    r0.z = (v0.z - mean) * rstd * ga[c0 + 2] + be[c0 + 2];
    r0.w = (v0.w - mean) * rstd * ga[c0 + 3] + be[c0 + 3];
    r1.x = (v1.x - mean) * rstd * ga[128 + c0 + 0] + be[128 + c0 + 0];
    r1.y = (v1.y - mean) * rstd * ga[128 + c0 + 1] + be[128 + c0 + 1];
    r1.z = (v1.z - mean) * rstd * ga[128 + c0 + 2] + be[128 + c0 + 2];
    r1.w = (v1.w - mean) * rstd * ga[128 + c0 + 3] + be[128 + c0 + 3];
    xo[lane] = r0;
    xo[32 + lane] = r1;
}

// ---------------- weight pre-transpose ----------------
__global__ void k_transpose(const float* __restrict__ Wx, const float* __restrict__ Wh) {
    int idx = blockIdx.x * 256 + threadIdx.x;
    if (idx >= 2 * 3 * 512 * NG) return;
    int dl  = idx / (512 * NG);
    int rem = idx % (512 * NG);
    int k   = rem / NG;
    int cp  = rem % NG;
    int j = cp >> 2, g = cp & 3;
    int n = g * 256 + j;
    float v = (k < 256) ? Wx[(size_t)dl * 256 * NG + (size_t)k * NG + n]
                        : Wh[(size_t)dl * 256 * NG + (size_t)(k - 256) * NG + n];
    g_Wt[idx] = v;
}

__global__ void k_zero() {
    int i = blockIdx.x * 256 + threadIdx.x;
    if (i < 2 * 3 * 2 * BB * HH) g_h[i] = 0.f;
    if (i < 2 * 3 * BB * HH)     g_c[i] = 0.f;
    if (i == 0) g_sync = 0u;
}

// ---------------- persistent wavefront LSTM (FFMA2) ----------------
// 384 blocks x 128 threads. Block tile 32m x 16 j-cols (64 gate floats).
// Thread tile: 4 m-rows x 1 j-col x 4 gates = 16 MAC/k as 8 FFMA2.
__global__ void __launch_bounds__(128, 3) k_lstm_persist(
    const float* __restrict__ blstm, float* __restrict__ out)
{
    const int bx    = blockIdx.x;
    const int ls    = bx >> 6;
    const int dir   = ls & 1;
    const int layer = ls >> 1;
    const int sub   = bx & 63;
    const int j0    = (sub & 15) * 16;
    const int m0    = (sub >> 4) * 32;
    const int tid   = threadIdx.x;
    const int j     = tid & 15;          // col group (1 col)
    const int mg    = tid >> 4;          // 0..7 -> rows m0+mg*4..+3
    const int dl    = dir * 3 + layer;

    __shared__ float sA[32][34];   // [k][m], pad 34 keeps 8B align for LDS.64
    __shared__ float sW[32][64];

    const float* Wl = g_Wt + (size_t)dl * 512 * NG + j0 * 4;
    const int col = j0 + j;
    const float* bbias = blstm + (size_t)dl * NG;
    const float bi  = bbias[col];
    const float bf_ = bbias[256 + col];
    const float bg  = bbias[512 + col];
    const float bo  = bbias[768 + col];
    float* cbuf = g_c + (size_t)dl * BB * HH;

    // fill-role indices: each thread loads 8 consecutive k for one m
    const int fm = tid >> 2;          // 0..31 row within tile
    const int fk = (tid & 3) * 8;     // k base within chunk

    const unsigned nb = gridDim.x;
    const int lprev = (layer > 0) ? (layer - 1) : 0;

    for (int w = 0; w < TSEQ + 2; ++w) {
        const int t = w - layer;
        if (t >= 0 && t < TSEQ) {
            const int tt = dir ? (TSEQ - 1 - t) : t;
            const int rp = t & 1, wp = rp ^ 1;
            const float* hin = g_h + (size_t)(dl * 2 + rp) * BB * HH;
            const float* cursrc = g_cur +
                (size_t)((dir * 2 + lprev) * 2 + (t & 1)) * BB * DD;
            float* curdst = g_cur +
                (size_t)((dir * 2 + layer) * 2 + (t & 1)) * BB * DD;

            u64 acc[4][2];
            const u64 zz = pk2(0.f, 0.f);
#pragma unroll
            for (int g = 0; g < 4; ++g) { acc[g][0] = zz; acc[g][1] = zz; }

            for (int kc = 0; kc < 512; kc += 32) {
                // --- fill sA: [k][m] ---
                {
                    int m = m0 + fm;
                    int kk = kc + fk;
                    float4 v0, v1;
                    if (kk < 256) {
                        const float* src = (layer == 0)
                            ? (g_x + ((size_t)m * TSEQ + tt) * DD + kk)
                            : (cursrc + (size_t)m * DD + kk);
                        v0 = *reinterpret_cast<const float4*>(src);
                        v1 = *reinterpret_cast<const float4*>(src + 4);
                    } else {
                        const float* src = hin + (size_t)m * HH + (kk - 256);
                        v0 = __ldcg(reinterpret_cast<const float4*>(src));
                        v1 = __ldcg(reinterpret_cast<const float4*>(src) + 1);
                    }
                    sA[fk + 0][fm] = v0.x; sA[fk + 1][fm] = v0.y;
                    sA[fk + 2][fm] = v0.z; sA[fk + 3][fm] = v0.w;
                    sA[fk + 4][fm] = v1.x; sA[fk + 5][fm] = v1.y;
                    sA[fk + 6][fm] = v1.z; sA[fk + 7][fm] = v1.w;
                }
                // --- fill sW ---
#pragma unroll
                for (int r = 0; r < 4; ++r) {
                    int e4 = tid + r * 128;
                    int k = e4 >> 4, c4 = e4 & 15;
                    *reinterpret_cast<float4*>(&sW[k][c4 * 4]) =
                        *reinterpret_cast<const float4*>(&Wl[(size_t)(kc + k) * NG + c4 * 4]);
                }
                __syncthreads();
#pragma unroll
                for (int k = 0; k < 32; ++k) {
                    u64 a01 = *reinterpret_cast<const u64*>(&sA[k][mg * 4]);
                    u64 a23 = *reinterpret_cast<const u64*>(&sA[k][mg * 4 + 2]);
                    float4 wv = *reinterpret_cast<const float4*>(&sW[k][j * 4]);
                    u64 w0 = pk2(wv.x, wv.x);
                    u64 w1 = pk2(wv.y, wv.y);
                    u64 w2 = pk2(wv.z, wv.z);
                    u64 w3 = pk2(wv.w, wv.w);
                    acc[0][0] = ff2(a01, w0, acc[0][0]); acc[0][1] = ff2(a23, w0, acc[0][1]);
                    acc[1][0] = ff2(a01, w1, acc[1][0]); acc[1][1] = ff2(a23, w1, acc[1][1]);
                    acc[2][0] = ff2(a01, w2, acc[2][0]); acc[2][1] = ff2(a23, w2, acc[2][1]);
                    acc[3][0] = ff2(a01, w3, acc[3][0]); acc[3][1] = ff2(a23, w3, acc[3][1]);
                }
                __syncthreads();
            }

            float* hout = g_h + (size_t)(dl * 2 + wp) * BB * HH;
#pragma unroll
            for (int p = 0; p < 2; ++p) {
                float2 zi = up2(acc[0][p]);
                float2 zf = up2(acc[1][p]);
                float2 zg = up2(acc[2][p]);
                float2 zo = up2(acc[3][p]);
#pragma unroll
                for (int h2 = 0; h2 < 2; ++h2) {
                    int m = m0 + mg * 4 + p * 2 + h2;
                    float vzi = (h2 ? zi.y : zi.x) + bi;
                    float vzf = (h2 ? zf.y : zf.x) + bf_;
                    float vzg = (h2 ? zg.y : zg.x) + bg;
                    float vzo = (h2 ? zo.y : zo.x) + bo;
                    float ig = 1.f / (1.f + expf(-vzi));
                    float fg = 1.f / (1.f + expf(-vzf));
                    float gg = tanhf(vzg);
                    float og = 1.f / (1.f + expf(-vzo));
                    float cp = cbuf[(size_t)m * HH + col];
                    float cn = fg * cp + ig * gg;
                    float hn = og * tanhf(cn);
                    cbuf[(size_t)m * HH + col] = cn;
                    hout[(size_t)m * HH + col] = hn;
                    float ain = (layer == 0)
                        ? g_x[((size_t)m * TSEQ + tt) * DD + col]
                        : __ldcg(cursrc + (size_t)m * DD + col);
                    float cu = ain + hn;
                    if (layer == 2)
                        out[((size_t)m * TSEQ + tt) * 512 + dir * 256 + col] = cu;
                    else
                        curdst[(size_t)m * DD + col] = cu;
                }
            }
        }

        // ---- grid barrier ----
        __syncthreads();
        __threadfence();
        if (tid == 0) {
            atomicAdd(&g_sync, 1u);
            unsigned target = nb * (unsigned)(w + 1);
            while (*(volatile unsigned*)&g_sync < target) __nanosleep(64);
        }
        __syncthreads();
    }
}

// ---------------- final states ----------------
__global__ void k_states(float* __restrict__ out) {
    int idx = blockIdx.x * 256 + threadIdx.x;
    if (idx >= 2 * 3 * BB * HH) return;
    int j  = idx & 255;
    int m  = (idx >> 8) & 127;
    int dl = idx >> 15;
    const size_t SEQ = (size_t)BB * TSEQ * 512;
    const size_t SH  = 2 * 3 * BB * HH;
    out[SEQ + idx]      = g_h[(size_t)(dl * 2 + 0) * BB * HH + (size_t)m * HH + j];
    out[SEQ + SH + idx] = g_c[(size_t)dl * BB * HH + (size_t)m * HH + j];
}

// ---------------- launch ----------------
extern "C" void kernel_launch(void* const* d_in, const int* in_sizes, int n_in,
                              void* d_out, int out_size) {
    const int*   tokens = (const int*)d_in[0];
    const float* E      = (const float*)d_in[1];
    const float* W3     = (const float*)d_in[2];
    const float* W5     = (const float*)d_in[3];
    const float* W7     = (const float*)d_in[4];
    const float* bconv  = (const float*)d_in[5];
    const float* gamma  = (const float*)d_in[6];
    const float* beta   = (const float*)d_in[7];
    const float* Wx     = (const float*)d_in[8];
    const float* Wh     = (const float*)d_in[9];
    const float* blstm  = (const float*)d_in[10];
    float* out = (float*)d_out;

    k_embed<<<BB * TSEQ, 64>>>(tokens, E);
    for (int it = 0; it < 2; ++it) {
        k_conv<<<dim3(TSEQ / 16, BB), 256>>>(W3, W5, W7, bconv, it);
        k_ln<<<BB * TSEQ / 8, 256>>>(gamma, beta, it);
    }
    k_transpose<<<(2 * 3 * 512 * NG + 255) / 256, 256>>>(Wx, Wh);
    k_zero<<<1536, 256>>>();
    k_lstm_persist<<<NBLK, 128>>>(blstm, out);
    k_states<<<768, 256>>>(out);
}